// round 1
// baseline (speedup 1.0000x reference)
#include <cuda_runtime.h>
#include <cstdint>

// Problem constants
#define Bd 256   // batch
#define Sd 512   // seq len
#define Cd 64    // input channels (layer 0)
#define Hd 128   // hidden
#define Gd 512   // 4*H gate columns
#define BPC 2    // batch rows per CTA in recurrence
#define REC_THREADS 512

// Scratch (device globals: allocation-free per harness rules)
__device__ float g_xg[(size_t)Sd * Bd * Gd];   // (S,B,4H) gate preactivations, reused by both layers
__device__ float g_y1[(size_t)Sd * Bd * Hd];   // (S,B,H) layer-0 outputs

// ---------------------------------------------------------------------------
// Input GEMM: out[m, g] = sum_k A[m,k] * W[g,k] + b1[g] + b2[g]
// m = s*Bd + b. X_LAYOUT=true: A is x with shape (B,S,C) -> row at (b*S+s)*K.
// X_LAYOUT=false: A row-major (m, K) (y1 buffer).
// 64x64 output tile per block, 256 threads, 4x4 microtile per thread.
// ---------------------------------------------------------------------------
template <int K, bool X_LAYOUT>
__global__ __launch_bounds__(256) void gemm_in_kernel(
    const float* __restrict__ A, const float* __restrict__ W,
    const float* __restrict__ b1, const float* __restrict__ b2,
    float* __restrict__ out)
{
    extern __shared__ float sm[];
    float* As = sm;            // [K][64] transposed A tile
    float* Ws = sm + K * 64;   // [K][64] transposed W tile

    const int tid = threadIdx.x;
    const int mt = blockIdx.x;
    const int nt = blockIdx.y;

    // Load A tile (transposed into [k][mi])
    for (int idx = tid; idx < 64 * K; idx += 256) {
        int mi = idx / K;
        int k  = idx % K;
        int m  = mt * 64 + mi;
        const float* arow;
        if (X_LAYOUT) {
            int s = m >> 8;        // m / Bd (Bd=256)
            int b = m & 255;       // m % Bd
            arow = A + ((size_t)b * Sd + s) * K;
        } else {
            arow = A + (size_t)m * K;
        }
        As[k * 64 + mi] = arow[k];
    }
    // Load W tile (transposed into [k][ni])
    for (int idx = tid; idx < 64 * K; idx += 256) {
        int ni = idx / K;
        int k  = idx % K;
        Ws[k * 64 + ni] = W[(size_t)(nt * 64 + ni) * K + k];
    }
    __syncthreads();

    float acc[4][4];
#pragma unroll
    for (int i = 0; i < 4; i++)
#pragma unroll
        for (int j = 0; j < 4; j++) acc[i][j] = 0.0f;

    const int m4 = (tid >> 4) * 4;
    const int n4 = (tid & 15) * 4;

#pragma unroll 16
    for (int k = 0; k < K; k++) {
        float4 a = *(const float4*)&As[k * 64 + m4];
        float4 w = *(const float4*)&Ws[k * 64 + n4];
        acc[0][0] = fmaf(a.x, w.x, acc[0][0]);
        acc[0][1] = fmaf(a.x, w.y, acc[0][1]);
        acc[0][2] = fmaf(a.x, w.z, acc[0][2]);
        acc[0][3] = fmaf(a.x, w.w, acc[0][3]);
        acc[1][0] = fmaf(a.y, w.x, acc[1][0]);
        acc[1][1] = fmaf(a.y, w.y, acc[1][1]);
        acc[1][2] = fmaf(a.y, w.z, acc[1][2]);
        acc[1][3] = fmaf(a.y, w.w, acc[1][3]);
        acc[2][0] = fmaf(a.z, w.x, acc[2][0]);
        acc[2][1] = fmaf(a.z, w.y, acc[2][1]);
        acc[2][2] = fmaf(a.z, w.z, acc[2][2]);
        acc[2][3] = fmaf(a.z, w.w, acc[2][3]);
        acc[3][0] = fmaf(a.w, w.x, acc[3][0]);
        acc[3][1] = fmaf(a.w, w.y, acc[3][1]);
        acc[3][2] = fmaf(a.w, w.z, acc[3][2]);
        acc[3][3] = fmaf(a.w, w.w, acc[3][3]);
    }

    const int g0 = nt * 64 + n4;
    float4 v1 = *(const float4*)&b1[g0];
    float4 v2 = *(const float4*)&b2[g0];
    float bx = v1.x + v2.x, by = v1.y + v2.y, bz = v1.z + v2.z, bw = v1.w + v2.w;

#pragma unroll
    for (int i = 0; i < 4; i++) {
        size_t m = (size_t)mt * 64 + m4 + i;
        float4 o;
        o.x = acc[i][0] + bx;
        o.y = acc[i][1] + by;
        o.z = acc[i][2] + bz;
        o.w = acc[i][3] + bw;
        *(float4*)&out[m * Gd + g0] = o;
    }
}

// ---------------------------------------------------------------------------
// LSTM recurrence (persistent over all S steps).
// Grid: Bd/BPC CTAs, 512 threads. Thread t owns gate column t.
// Whh[t, 0:64] in registers; Whh[:, 64:128] in smem transposed [k][t].
// h vectors + gate staging in smem; c in registers of threads t < BPC*Hd.
// ---------------------------------------------------------------------------
__device__ __forceinline__ float sigf(float x) {
    return 1.0f / (1.0f + __expf(-x));
}

__global__ __launch_bounds__(REC_THREADS, 1) void lstm_rec_kernel(
    const float* __restrict__ xg,     // (S, B, 4H) preactivations
    const float* __restrict__ Whh,    // (4H, H)
    float* __restrict__ y_all,        // (S, B, H) or nullptr
    float* __restrict__ y_last)       // (B, H) used if y_all == nullptr
{
    extern __shared__ float smem[];
    float* WshT  = smem;                       // [64][512] Whh[:,64:128] transposed
    float* hbuf  = smem + 64 * Gd;             // [BPC][Hd]
    float* gates = smem + 64 * Gd + BPC * Hd;  // [BPC][Gd]

    const int t  = threadIdx.x;
    const int b0 = blockIdx.x * BPC;

    // Register half of the weights: Whh[t][0:64] as 16 float4
    float4 w4[16];
    {
        const float4* wrow = (const float4*)(Whh + (size_t)t * Hd);
#pragma unroll
        for (int i = 0; i < 16; i++) w4[i] = wrow[i];
    }
    // Smem half, transposed: WshT[k*512 + col] = Whh[col][64+k]
    for (int idx = t; idx < 64 * Gd; idx += REC_THREADS) {
        int k   = idx >> 9;
        int col = idx & 511;
        WshT[idx] = Whh[(size_t)col * Hd + 64 + k];
    }
    for (int idx = t; idx < BPC * Hd; idx += REC_THREADS) hbuf[idx] = 0.0f;

    float creg = 0.0f;  // cell state for (b = t>>7, u = t&127) when t < BPC*Hd
    __syncthreads();

    const float4* h40 = (const float4*)(hbuf);
    const float4* h41 = (const float4*)(hbuf + Hd);

    for (int s = 0; s < Sd; s++) {
        // Gate preactivation input (bias already folded in by the GEMM)
        float xv0 = xg[((size_t)s * Bd + b0) * Gd + t];
        float xv1 = xg[((size_t)s * Bd + b0 + 1) * Gd + t];

        float acc0 = 0.0f, acc1 = 0.0f;

        // k = 0..63 : register weights
#pragma unroll
        for (int i = 0; i < 16; i++) {
            float4 w  = w4[i];
            float4 ha = h40[i];
            float4 hb = h41[i];
            acc0 = fmaf(w.x, ha.x, acc0);
            acc1 = fmaf(w.x, hb.x, acc1);
            acc0 = fmaf(w.y, ha.y, acc0);
            acc1 = fmaf(w.y, hb.y, acc1);
            acc0 = fmaf(w.z, ha.z, acc0);
            acc1 = fmaf(w.z, hb.z, acc1);
            acc0 = fmaf(w.w, ha.w, acc0);
            acc1 = fmaf(w.w, hb.w, acc1);
        }
        // k = 64..127 : smem weights (lane-contiguous, conflict-free)
#pragma unroll
        for (int i = 0; i < 16; i++) {
            float4 ha = h40[16 + i];
            float4 hb = h41[16 + i];
            float w0 = WshT[(4 * i + 0) * Gd + t];
            float w1 = WshT[(4 * i + 1) * Gd + t];
            float w2 = WshT[(4 * i + 2) * Gd + t];
            float w3 = WshT[(4 * i + 3) * Gd + t];
            acc0 = fmaf(w0, ha.x, acc0);
            acc1 = fmaf(w0, hb.x, acc1);
            acc0 = fmaf(w1, ha.y, acc0);
            acc1 = fmaf(w1, hb.y, acc1);
            acc0 = fmaf(w2, ha.z, acc0);
            acc1 = fmaf(w2, hb.z, acc1);
            acc0 = fmaf(w3, ha.w, acc0);
            acc1 = fmaf(w3, hb.w, acc1);
        }

        gates[t]      = acc0 + xv0;
        gates[Gd + t] = acc1 + xv1;
        __syncthreads();  // gates complete; all hbuf reads for this step done

        if (t < BPC * Hd) {
            const int b = t >> 7;
            const int u = t & 127;
            const float* gb = gates + b * Gd;
            float i_ = sigf(gb[u]);
            float f_ = sigf(gb[Hd + u]);
            float g_ = tanhf(gb[2 * Hd + u]);
            float o_ = sigf(gb[3 * Hd + u]);
            creg = fmaf(f_, creg, i_ * g_);
            float hn = o_ * tanhf(creg);
            hbuf[b * Hd + u] = hn;
            if (y_all) {
                y_all[((size_t)s * Bd + b0 + b) * Hd + u] = hn;
            } else if (s == Sd - 1) {
                y_last[(size_t)(b0 + b) * Hd + u] = hn;
            }
        }
        __syncthreads();  // h published before next step reads it
    }
}

// ---------------------------------------------------------------------------
// Launch
// ---------------------------------------------------------------------------
extern "C" void kernel_launch(void* const* d_in, const int* in_sizes, int n_in,
                              void* d_out, int out_size)
{
    const float* x    = (const float*)d_in[0];
    const float* Wih0 = (const float*)d_in[1];
    const float* Whh0 = (const float*)d_in[2];
    const float* bih0 = (const float*)d_in[3];
    const float* bhh0 = (const float*)d_in[4];
    const float* Wih1 = (const float*)d_in[5];
    const float* Whh1 = (const float*)d_in[6];
    const float* bih1 = (const float*)d_in[7];
    const float* bhh1 = (const float*)d_in[8];
    float* out = (float*)d_out;

    float* xg = nullptr;
    float* y1 = nullptr;
    cudaGetSymbolAddress((void**)&xg, g_xg);
    cudaGetSymbolAddress((void**)&y1, g_y1);

    const int smem_g0  = 2 * Cd * 64 * (int)sizeof(float);   // 32 KB
    const int smem_g1  = 2 * Hd * 64 * (int)sizeof(float);   // 64 KB
    const int smem_rec = (64 * Gd + BPC * Hd + BPC * Gd) * (int)sizeof(float); // ~133 KB

    cudaFuncSetAttribute((const void*)gemm_in_kernel<Cd, true>,
                         cudaFuncAttributeMaxDynamicSharedMemorySize, smem_g0);
    cudaFuncSetAttribute((const void*)gemm_in_kernel<Hd, false>,
                         cudaFuncAttributeMaxDynamicSharedMemorySize, smem_g1);
    cudaFuncSetAttribute((const void*)lstm_rec_kernel,
                         cudaFuncAttributeMaxDynamicSharedMemorySize, smem_rec);

    dim3 ggrid((Sd * Bd) / 64, Gd / 64);

    // Layer 0: input GEMM then recurrence (writes all h to y1)
    gemm_in_kernel<Cd, true><<<ggrid, 256, smem_g0>>>(x, Wih0, bih0, bhh0, xg);
    lstm_rec_kernel<<<Bd / BPC, REC_THREADS, smem_rec>>>(xg, Whh0, y1, nullptr);

    // Layer 1: input GEMM on y1, recurrence writes only final h to d_out
    gemm_in_kernel<Hd, false><<<ggrid, 256, smem_g1>>>(y1, Wih1, bih1, bhh1, xg);
    lstm_rec_kernel<<<Bd / BPC, REC_THREADS, smem_rec>>>(xg, Whh1, nullptr, out);
}

// round 2
// speedup vs baseline: 1.0673x; 1.0673x over previous
#include <cuda_runtime.h>
#include <cstdint>

// Problem constants
#define Bd 256   // batch
#define Sd 512   // seq len
#define Cd 64    // input channels (layer 0)
#define Hd 128   // hidden
#define Gd 512   // 4*H gate columns
#define BPC 2    // batch rows per CTA in recurrence
#define REC_THREADS 512

typedef unsigned long long u64;

// Scratch (device globals: allocation-free per harness rules)
__device__ float g_xg[(size_t)Sd * Bd * Gd];   // (S,B,4H) gate preactivations
__device__ float g_y1[(size_t)Sd * Bd * Hd];   // (S,B,H) layer-0 outputs

// ---------------------------------------------------------------------------
// Packed fp32x2 helpers (Blackwell FFMA2 via PTX fma.rn.f32x2)
// ---------------------------------------------------------------------------
__device__ __forceinline__ u64 pack2(float x, float y) {
    u64 r; asm("mov.b64 %0, {%1,%2};" : "=l"(r) : "f"(x), "f"(y)); return r;
}
__device__ __forceinline__ void unpack2(u64 v, float& x, float& y) {
    asm("mov.b64 {%0,%1}, %2;" : "=f"(x), "=f"(y) : "l"(v));
}
__device__ __forceinline__ u64 fma2(u64 a, u64 b, u64 c) {
    u64 d; asm("fma.rn.f32x2 %0, %1, %2, %3;" : "=l"(d) : "l"(a), "l"(b), "l"(c)); return d;
}

// ---------------------------------------------------------------------------
// Input GEMM: out[m, g] = sum_k A[m,k] * W[g,k] + b1[g] + b2[g]
// Tile: 128 (m) x 64 (n), 256 threads, microtile 4m x 8n with f32x2 over
// n-pairs. A tile row-major (stride K+1), W tile transposed [k][64].
// All smem fills conflict-free; A fill coalesced.
// X_LAYOUT=true: A is x (B,S,C): row for m=(s*Bd+b) at (b*Sd+s)*K.
// ---------------------------------------------------------------------------
template <int K, bool X_LAYOUT>
__global__ __launch_bounds__(256) void gemm_in_kernel(
    const float* __restrict__ A, const float* __restrict__ W,
    const float* __restrict__ b1, const float* __restrict__ b2,
    float* __restrict__ out)
{
    constexpr int SAK = K + 1;           // padded A stride (kills compute conflicts)
    extern __shared__ float sm[];
    float* As = sm;                      // [128][SAK] row-major
    float* Ws = sm + 128 * SAK;          // [K][64]    transposed

    const int tid = threadIdx.x;
    const int mt  = blockIdx.x;
    const int nt  = blockIdx.y;

    // A fill: lanes walk k fastest -> coalesced LDG, conflict-free STS.
    for (int idx = tid; idx < 128 * K; idx += 256) {
        int mi = idx / K;
        int k  = idx % K;
        int m  = mt * 128 + mi;
        const float* arow;
        if (X_LAYOUT) {
            int s = m >> 8;          // m / Bd
            int b = m & 255;         // m % Bd
            arow = A + ((size_t)b * Sd + s) * K;
        } else {
            arow = A + (size_t)m * K;
        }
        As[mi * SAK + k] = arow[k];
    }
    // W fill: lanes walk ni fastest -> conflict-free STS (LDG L1-cached rows).
    for (int idx = tid; idx < 64 * K; idx += 256) {
        int ni = idx & 63;
        int k  = idx >> 6;
        Ws[k * 64 + ni] = W[(size_t)(nt * 64 + ni) * K + k];
    }
    __syncthreads();

    const int m0 = (tid >> 3) * 4;   // 32 m-threads x 4 rows
    const int n0 = (tid & 7) * 8;    // 8 n-threads x 8 cols (4 n-pairs)

    u64 acc[4][4];
#pragma unroll
    for (int i = 0; i < 4; i++)
#pragma unroll
        for (int j = 0; j < 4; j++) acc[i][j] = 0ULL;

#pragma unroll 8
    for (int k = 0; k < K; k++) {
        const u64* wp = (const u64*)&Ws[k * 64 + n0];   // 4 natural n-pairs
        u64 w0 = wp[0], w1 = wp[1], w2 = wp[2], w3 = wp[3];
#pragma unroll
        for (int i = 0; i < 4; i++) {
            float a = As[(m0 + i) * SAK + k];
            u64 av = pack2(a, a);
            acc[i][0] = fma2(av, w0, acc[i][0]);
            acc[i][1] = fma2(av, w1, acc[i][1]);
            acc[i][2] = fma2(av, w2, acc[i][2]);
            acc[i][3] = fma2(av, w3, acc[i][3]);
        }
    }

    // Bias + store
    const int g0 = nt * 64 + n0;
    float bias[8];
#pragma unroll
    for (int j = 0; j < 8; j++) bias[j] = b1[g0 + j] + b2[g0 + j];

#pragma unroll
    for (int i = 0; i < 4; i++) {
        float o[8];
#pragma unroll
        for (int j = 0; j < 4; j++) unpack2(acc[i][j], o[2 * j], o[2 * j + 1]);
        float4 v0, v1;
        v0.x = o[0] + bias[0]; v0.y = o[1] + bias[1];
        v0.z = o[2] + bias[2]; v0.w = o[3] + bias[3];
        v1.x = o[4] + bias[4]; v1.y = o[5] + bias[5];
        v1.z = o[6] + bias[6]; v1.w = o[7] + bias[7];
        size_t m = (size_t)mt * 128 + m0 + i;
        *(float4*)&out[m * Gd + g0]     = v0;
        *(float4*)&out[m * Gd + g0 + 4] = v1;
    }
}

// ---------------------------------------------------------------------------
// LSTM recurrence (persistent over all S steps), f32x2 over k-pairs.
// Grid: Bd/BPC CTAs, 512 threads. Thread t owns gate column t.
// Whh[t, 0:64] (32 pairs) in registers; Whh[:, 64:128] pairs in smem
// transposed [kp][col]. h in smem (pairs are contiguous), c in registers.
// ---------------------------------------------------------------------------
__device__ __forceinline__ float sigf(float x) {
    return 1.0f / (1.0f + __expf(-x));
}

__global__ __launch_bounds__(REC_THREADS, 1) void lstm_rec_kernel(
    const float* __restrict__ xg,     // (S, B, 4H)
    const float* __restrict__ Whh,    // (4H, H)
    float* __restrict__ y_all,        // (S, B, H) or nullptr
    float* __restrict__ y_last)       // (B, H) if y_all == nullptr
{
    extern __shared__ float smem[];
    u64*   WshP  = (u64*)smem;                          // [32][512] k-pairs 32..63
    float* hbuf  = smem + 32 * Gd * 2;                  // [BPC][Hd]
    float* gates = smem + 32 * Gd * 2 + BPC * Hd;       // [BPC][Gd]

    const int t  = threadIdx.x;
    const int b0 = blockIdx.x * BPC;

    // Register weights: Whh[t][0:64] as 32 packed pairs
    u64 wreg[32];
    {
        const u64* wrow = (const u64*)(Whh + (size_t)t * Hd);
#pragma unroll
        for (int i = 0; i < 32; i++) wreg[i] = wrow[i];
    }
    // Smem weights: pair kp (k = 64+2kp, 65+2kp) for every column
    for (int idx = t; idx < 32 * Gd; idx += REC_THREADS) {
        int kp  = idx >> 9;
        int col = idx & 511;
        const float* w = Whh + (size_t)col * Hd + 64 + 2 * kp;
        WshP[idx] = pack2(w[0], w[1]);
    }
    for (int idx = t; idx < BPC * Hd; idx += REC_THREADS) hbuf[idx] = 0.0f;

    float creg = 0.0f;
    __syncthreads();

    const u64* hp0 = (const u64*)(hbuf);        // 64 k-pairs of batch b0
    const u64* hp1 = (const u64*)(hbuf + Hd);   // batch b0+1

    for (int s = 0; s < Sd; s++) {
        float xv0 = xg[((size_t)s * Bd + b0) * Gd + t];
        float xv1 = xg[((size_t)s * Bd + b0 + 1) * Gd + t];

        u64 a0a = 0ULL, a0b = 0ULL, a1a = 0ULL, a1b = 0ULL;

        // k = 0..63 : register weight pairs (4 independent chains)
#pragma unroll
        for (int i = 0; i < 32; i += 2) {
            u64 h0e = hp0[i], h1e = hp1[i];
            u64 h0o = hp0[i + 1], h1o = hp1[i + 1];
            a0a = fma2(wreg[i],     h0e, a0a);
            a1a = fma2(wreg[i],     h1e, a1a);
            a0b = fma2(wreg[i + 1], h0o, a0b);
            a1b = fma2(wreg[i + 1], h1o, a1b);
        }
        // k = 64..127 : smem weight pairs (lane-contiguous LDS.64)
#pragma unroll
        for (int i = 0; i < 32; i += 2) {
            u64 we = WshP[i * Gd + t];
            u64 wo = WshP[(i + 1) * Gd + t];
            u64 h0e = hp0[32 + i], h1e = hp1[32 + i];
            u64 h0o = hp0[33 + i], h1o = hp1[33 + i];
            a0a = fma2(we, h0e, a0a);
            a1a = fma2(we, h1e, a1a);
            a0b = fma2(wo, h0o, a0b);
            a1b = fma2(wo, h1o, a1b);
        }

        float x0, y0, x1, y1, x2, y2, x3, y3;
        unpack2(a0a, x0, y0); unpack2(a0b, x1, y1);
        unpack2(a1a, x2, y2); unpack2(a1b, x3, y3);
        gates[t]      = xv0 + (x0 + y0) + (x1 + y1);
        gates[Gd + t] = xv1 + (x2 + y2) + (x3 + y3);
        __syncthreads();

        if (t < BPC * Hd) {
            const int b = t >> 7;
            const int u = t & 127;
            const float* gb = gates + b * Gd;
            float i_ = sigf(gb[u]);
            float f_ = sigf(gb[Hd + u]);
            float g_ = tanhf(gb[2 * Hd + u]);
            float o_ = sigf(gb[3 * Hd + u]);
            creg = fmaf(f_, creg, i_ * g_);
            float hn = o_ * tanhf(creg);
            hbuf[b * Hd + u] = hn;
            if (y_all) {
                y_all[((size_t)s * Bd + b0 + b) * Hd + u] = hn;
            } else if (s == Sd - 1) {
                y_last[(size_t)(b0 + b) * Hd + u] = hn;
            }
        }
        __syncthreads();
    }
}

// ---------------------------------------------------------------------------
// Launch
// ---------------------------------------------------------------------------
extern "C" void kernel_launch(void* const* d_in, const int* in_sizes, int n_in,
                              void* d_out, int out_size)
{
    const float* x    = (const float*)d_in[0];
    const float* Wih0 = (const float*)d_in[1];
    const float* Whh0 = (const float*)d_in[2];
    const float* bih0 = (const float*)d_in[3];
    const float* bhh0 = (const float*)d_in[4];
    const float* Wih1 = (const float*)d_in[5];
    const float* Whh1 = (const float*)d_in[6];
    const float* bih1 = (const float*)d_in[7];
    const float* bhh1 = (const float*)d_in[8];
    float* out = (float*)d_out;

    float* xg = nullptr;
    float* y1 = nullptr;
    cudaGetSymbolAddress((void**)&xg, g_xg);
    cudaGetSymbolAddress((void**)&y1, g_y1);

    const int smem_g0  = (128 * (Cd + 1) + Cd * 64) * (int)sizeof(float);   // ~49 KB
    const int smem_g1  = (128 * (Hd + 1) + Hd * 64) * (int)sizeof(float);   // ~99 KB
    const int smem_rec = (32 * Gd * 2 + BPC * Hd + BPC * Gd) * (int)sizeof(float); // ~133 KB

    cudaFuncSetAttribute((const void*)gemm_in_kernel<Cd, true>,
                         cudaFuncAttributeMaxDynamicSharedMemorySize, smem_g0);
    cudaFuncSetAttribute((const void*)gemm_in_kernel<Hd, false>,
                         cudaFuncAttributeMaxDynamicSharedMemorySize, smem_g1);
    cudaFuncSetAttribute((const void*)lstm_rec_kernel,
                         cudaFuncAttributeMaxDynamicSharedMemorySize, smem_rec);

    dim3 ggrid((Sd * Bd) / 128, Gd / 64);

    // Layer 0
    gemm_in_kernel<Cd, true><<<ggrid, 256, smem_g0>>>(x, Wih0, bih0, bhh0, xg);
    lstm_rec_kernel<<<Bd / BPC, REC_THREADS, smem_rec>>>(xg, Whh0, y1, nullptr);

    // Layer 1
    gemm_in_kernel<Hd, false><<<ggrid, 256, smem_g1>>>(y1, Wih1, bih1, bhh1, xg);
    lstm_rec_kernel<<<Bd / BPC, REC_THREADS, smem_rec>>>(xg, Whh1, nullptr, out);
}

// round 3
// speedup vs baseline: 1.3918x; 1.3040x over previous
#include <cuda_runtime.h>
#include <cstdint>

#define Bd 256
#define Sd 512
#define Cd 64
#define Hd 128
#define Gd 512
#define BPC 2
#define REC_THREADS 512

typedef unsigned long long u64;

__device__ float g_xg[(size_t)Sd * Bd * Gd];
__device__ float g_y1[(size_t)Sd * Bd * Hd];

__device__ __forceinline__ u64 pack2(float x, float y) {
    u64 r; asm("mov.b64 %0, {%1,%2};" : "=l"(r) : "f"(x), "f"(y)); return r;
}
__device__ __forceinline__ void unpack2(u64 v, float& x, float& y) {
    asm("mov.b64 {%0,%1}, %2;" : "=f"(x), "=f"(y) : "l"(v));
}
__device__ __forceinline__ u64 fma2(u64 a, u64 b, u64 c) {
    u64 d; asm("fma.rn.f32x2 %0, %1, %2, %3;" : "=l"(d) : "l"(a), "l"(b), "l"(c)); return d;
}
__device__ __forceinline__ float tanh_fast(float x) {
    float y; asm("tanh.approx.f32 %0, %1;" : "=f"(y) : "f"(x)); return y;
}
__device__ __forceinline__ float sig_fast(float x) {
    return fmaf(0.5f, tanh_fast(0.5f * x), 0.5f);
}

// ---------------------------------------------------------------------------
// Input GEMM: out[m,g] = sum_k A[m,k]*W[g,k] + b1[g] + b2[g]
// 128m x 64n tile, kc=32 double-buffered, 256 threads, 4m x 8n microtile.
// ---------------------------------------------------------------------------
template <int K, bool X_LAYOUT>
__global__ __launch_bounds__(256) void gemm_in_kernel(
    const float* __restrict__ A, const float* __restrict__ W,
    const float* __restrict__ b1, const float* __restrict__ b2,
    float* __restrict__ out)
{
    constexpr int KC = 32;
    constexpr int NC = K / KC;
    constexpr int SA = KC + 1;   // A tile row stride (m-major [128][SA])
    constexpr int SW = 66;       // W tile k-row stride ([KC][SW]), 8B-aligned pairs

    extern __shared__ float sm[];
    float* As = sm;                      // [2][128*SA]
    float* Ws = sm + 2 * 128 * SA;       // [2][KC*SW]

    const int tid = threadIdx.x;
    const int mt  = blockIdx.x;
    const int nt  = blockIdx.y;

    const int kk  = tid & 31;            // staging k within chunk
    const int mr0 = tid >> 5;            // staging A row base (stride 8)
    const int nr0 = tid >> 5;            // staging W row base (stride 8)

    float aR[16], wR[8];

    auto ldg_chunk = [&](int c) {
        const int k0 = c * KC;
#pragma unroll
        for (int j = 0; j < 16; j++) {
            int mrow = mr0 + 8 * j;
            int m = mt * 128 + mrow;
            const float* arow;
            if (X_LAYOUT) {
                int s = m >> 8, b = m & 255;
                arow = A + ((size_t)b * Sd + s) * K;
            } else {
                arow = A + (size_t)m * K;
            }
            aR[j] = arow[k0 + kk];
        }
#pragma unroll
        for (int j = 0; j < 8; j++) {
            int ni = nr0 + 8 * j;
            wR[j] = W[(size_t)(nt * 64 + ni) * K + k0 + kk];
        }
    };
    auto sts_chunk = [&](int buf) {
        float* Ab = As + buf * 128 * SA;
        float* Wb = Ws + buf * KC * SW;
#pragma unroll
        for (int j = 0; j < 16; j++) Ab[(mr0 + 8 * j) * SA + kk] = aR[j];
#pragma unroll
        for (int j = 0; j < 8; j++)  Wb[kk * SW + nr0 + 8 * j] = wR[j];
    };

    const int m0 = (tid >> 3) * 4;
    const int n0 = (tid & 7) * 8;

    u64 acc[4][4];
#pragma unroll
    for (int i = 0; i < 4; i++)
#pragma unroll
        for (int j = 0; j < 4; j++) acc[i][j] = 0ULL;

    ldg_chunk(0);
    sts_chunk(0);
    __syncthreads();

    for (int c = 0; c < NC; c++) {
        if (c + 1 < NC) ldg_chunk(c + 1);

        const float* Ab = As + (c & 1) * 128 * SA;
        const float* Wb = Ws + (c & 1) * KC * SW;
#pragma unroll
        for (int k = 0; k < KC; k++) {
            const u64* wp = (const u64*)&Wb[k * SW + n0];
            u64 w0 = wp[0], w1 = wp[1], w2 = wp[2], w3 = wp[3];
#pragma unroll
            for (int i = 0; i < 4; i++) {
                float a = Ab[(m0 + i) * SA + k];
                u64 av = pack2(a, a);
                acc[i][0] = fma2(av, w0, acc[i][0]);
                acc[i][1] = fma2(av, w1, acc[i][1]);
                acc[i][2] = fma2(av, w2, acc[i][2]);
                acc[i][3] = fma2(av, w3, acc[i][3]);
            }
        }
        if (c + 1 < NC) {
            __syncthreads();
            sts_chunk((c + 1) & 1);
            __syncthreads();
        }
    }

    const int g0 = nt * 64 + n0;
    float bias[8];
#pragma unroll
    for (int j = 0; j < 8; j++) bias[j] = b1[g0 + j] + b2[g0 + j];

#pragma unroll
    for (int i = 0; i < 4; i++) {
        float o[8];
#pragma unroll
        for (int j = 0; j < 4; j++) unpack2(acc[i][j], o[2 * j], o[2 * j + 1]);
        float4 v0, v1;
        v0.x = o[0] + bias[0]; v0.y = o[1] + bias[1];
        v0.z = o[2] + bias[2]; v0.w = o[3] + bias[3];
        v1.x = o[4] + bias[4]; v1.y = o[5] + bias[5];
        v1.z = o[6] + bias[6]; v1.w = o[7] + bias[7];
        size_t m = (size_t)mt * 128 + m0 + i;
        *(float4*)&out[m * Gd + g0]     = v0;
        *(float4*)&out[m * Gd + g0 + 4] = v1;
    }
}

// ---------------------------------------------------------------------------
// LSTM recurrence. 512 threads, BPC=2, grid 128.
// Quad {4u..4u+3} owns gate cols {u, H+u, 2H+u, 3H+u} (i,f,g,o of unit u).
// Whh[col][0:64] in regs (32 pairs); [64:128] in smem [i4][threadid] as 16B
// quads. h double-buffered in smem, read as ulonglong2 broadcasts.
// Epilogue via intra-quad shfl; ONE barrier per step.
// ---------------------------------------------------------------------------
__global__ __launch_bounds__(REC_THREADS, 1) void lstm_rec_kernel(
    const float* __restrict__ xg, const float* __restrict__ Whh,
    float* __restrict__ y_all, float* __restrict__ y_last)
{
    extern __shared__ float smem[];
    ulonglong2* Wsh4 = (ulonglong2*)smem;        // [16][512] : k-quad i4 for thread t
    float* hbuf = smem + 16 * Gd * 4;            // [2][BPC][Hd]

    const int t  = threadIdx.x;
    const int r  = t & 3;
    const int u  = t >> 2;
    const int col = r * Hd + u;
    const int b0 = blockIdx.x * BPC;
    const int qb = (t & 31) & ~3;                // quad base lane in warp

    // Register weights: Whh[col][0:64] as 32 pairs
    u64 wreg[32];
    {
        const u64* wrow = (const u64*)(Whh + (size_t)col * Hd);
#pragma unroll
        for (int i = 0; i < 32; i++) wreg[i] = wrow[i];
    }
    // Smem weights: Wsh4[i4*512 + tt] = Whh[col(tt)][64+4*i4 .. +3]
    for (int idx = t; idx < 16 * Gd; idx += REC_THREADS) {
        int i4 = idx >> 9, tt = idx & 511;
        int cc = (tt & 3) * Hd + (tt >> 2);
        Wsh4[idx] = *(const ulonglong2*)(Whh + (size_t)cc * Hd + 64 + 4 * i4);
    }
    hbuf[t] = 0.0f;   // zero both h buffers (2*BPC*Hd = 512 floats)

    float creg = 0.0f;
    __syncthreads();

    float xv0 = xg[(size_t)b0 * Gd + col];
    float xv1 = xg[((size_t)b0 + 1) * Gd + col];

    for (int s = 0; s < Sd; s++) {
        float nx0 = 0.0f, nx1 = 0.0f;
        if (s + 1 < Sd) {   // prefetch next step's x-preactivations
            nx0 = xg[((size_t)(s + 1) * Bd + b0) * Gd + col];
            nx1 = xg[((size_t)(s + 1) * Bd + b0 + 1) * Gd + col];
        }
        const int p = s & 1;
        const ulonglong2* h0 = (const ulonglong2*)(hbuf + p * (BPC * Hd));
        const ulonglong2* h1 = (const ulonglong2*)(hbuf + p * (BPC * Hd) + Hd);

        u64 a0a = 0ULL, a0b = 0ULL, a1a = 0ULL, a1b = 0ULL;
#pragma unroll
        for (int i4 = 0; i4 < 16; i4++) {       // k = 0..63 (register weights)
            ulonglong2 hA = h0[i4], hB = h1[i4];
            a0a = fma2(wreg[2 * i4],     hA.x, a0a);
            a1a = fma2(wreg[2 * i4],     hB.x, a1a);
            a0b = fma2(wreg[2 * i4 + 1], hA.y, a0b);
            a1b = fma2(wreg[2 * i4 + 1], hB.y, a1b);
        }
#pragma unroll
        for (int i4 = 0; i4 < 16; i4++) {       // k = 64..127 (smem weights)
            ulonglong2 wv = Wsh4[i4 * Gd + t];
            ulonglong2 hA = h0[16 + i4], hB = h1[16 + i4];
            a0a = fma2(wv.x, hA.x, a0a);
            a1a = fma2(wv.x, hB.x, a1a);
            a0b = fma2(wv.y, hA.y, a0b);
            a1b = fma2(wv.y, hB.y, a1b);
        }

        float e0, f0, e1, f1, e2, f2, e3, f3;
        unpack2(a0a, e0, f0); unpack2(a0b, e1, f1);
        unpack2(a1a, e2, f2); unpack2(a1b, e3, f3);
        float p0 = xv0 + (e0 + f0) + (e1 + f1);   // gate preact, batch0
        float p1 = xv1 + (e2 + f2) + (e3 + f3);   // batch1

        // per-lane activation (r==2 is tanh gate)
        float v0 = (r == 2) ? tanh_fast(p0) : sig_fast(p0);
        float v1 = (r == 2) ? tanh_fast(p1) : sig_fast(p1);

        // quad transpose via shfl: gather i,f,g,o for both batches
        float i0 = __shfl_sync(0xffffffffu, v0, qb + 0);
        float ff0 = __shfl_sync(0xffffffffu, v0, qb + 1);
        float gg0 = __shfl_sync(0xffffffffu, v0, qb + 2);
        float o0 = __shfl_sync(0xffffffffu, v0, qb + 3);
        float i1 = __shfl_sync(0xffffffffu, v1, qb + 0);
        float ff1 = __shfl_sync(0xffffffffu, v1, qb + 1);
        float gg1 = __shfl_sync(0xffffffffu, v1, qb + 2);
        float o1 = __shfl_sync(0xffffffffu, v1, qb + 3);

        // lane r==0 owns (batch0, u); lane r==1 owns (batch1, u)
        float iv = (r == 0) ? i0 : i1;
        float fv = (r == 0) ? ff0 : ff1;
        float gv = (r == 0) ? gg0 : gg1;
        float ov = (r == 0) ? o0 : o1;
        creg = fmaf(fv, creg, iv * gv);
        float hn = ov * tanh_fast(creg);

        float* hnext = hbuf + (p ^ 1) * (BPC * Hd);
        if (r < 2) {
            hnext[r * Hd + u] = hn;
            if (y_all) {
                y_all[((size_t)s * Bd + b0 + r) * Hd + u] = hn;
            } else if (s == Sd - 1) {
                y_last[(size_t)(b0 + r) * Hd + u] = hn;
            }
        }
        xv0 = nx0; xv1 = nx1;
        __syncthreads();
    }
}

// ---------------------------------------------------------------------------
extern "C" void kernel_launch(void* const* d_in, const int* in_sizes, int n_in,
                              void* d_out, int out_size)
{
    const float* x    = (const float*)d_in[0];
    const float* Wih0 = (const float*)d_in[1];
    const float* Whh0 = (const float*)d_in[2];
    const float* bih0 = (const float*)d_in[3];
    const float* bhh0 = (const float*)d_in[4];
    const float* Wih1 = (const float*)d_in[5];
    const float* Whh1 = (const float*)d_in[6];
    const float* bih1 = (const float*)d_in[7];
    const float* bhh1 = (const float*)d_in[8];
    float* out = (float*)d_out;

    float* xg = nullptr;
    float* y1 = nullptr;
    cudaGetSymbolAddress((void**)&xg, g_xg);
    cudaGetSymbolAddress((void**)&y1, g_y1);

    const int smem_gemm = (2 * 128 * 33 + 2 * 32 * 66) * (int)sizeof(float);   // ~50 KB
    const int smem_rec  = 16 * Gd * 16 + 2 * BPC * Hd * (int)sizeof(float);    // ~133 KB

    cudaFuncSetAttribute((const void*)gemm_in_kernel<Cd, true>,
                         cudaFuncAttributeMaxDynamicSharedMemorySize, smem_gemm);
    cudaFuncSetAttribute((const void*)gemm_in_kernel<Hd, false>,
                         cudaFuncAttributeMaxDynamicSharedMemorySize, smem_gemm);
    cudaFuncSetAttribute((const void*)lstm_rec_kernel,
                         cudaFuncAttributeMaxDynamicSharedMemorySize, smem_rec);

    dim3 ggrid((Sd * Bd) / 128, Gd / 64);

    gemm_in_kernel<Cd, true><<<ggrid, 256, smem_gemm>>>(x, Wih0, bih0, bhh0, xg);
    lstm_rec_kernel<<<Bd / BPC, REC_THREADS, smem_rec>>>(xg, Whh0, y1, nullptr);

    gemm_in_kernel<Hd, false><<<ggrid, 256, smem_gemm>>>(y1, Wih1, bih1, bhh1, xg);
    lstm_rec_kernel<<<Bd / BPC, REC_THREADS, smem_rec>>>(xg, Whh1, nullptr, out);
}

// round 4
// speedup vs baseline: 1.3959x; 1.0030x over previous
#include <cuda_runtime.h>
#include <cstdint>

#define Bd 256
#define Sd 512
#define Cd 64
#define Hd 128
#define Gd 512
#define BPC 2
#define REC_THREADS 512

typedef unsigned long long u64;

__device__ float g_xg[(size_t)Sd * Bd * Gd];
__device__ float g_y1[(size_t)Sd * Bd * Hd];

__device__ __forceinline__ u64 pack2(float x, float y) {
    u64 r; asm("mov.b64 %0, {%1,%2};" : "=l"(r) : "f"(x), "f"(y)); return r;
}
__device__ __forceinline__ void unpack2(u64 v, float& x, float& y) {
    asm("mov.b64 {%0,%1}, %2;" : "=f"(x), "=f"(y) : "l"(v));
}
__device__ __forceinline__ u64 fma2(u64 a, u64 b, u64 c) {
    u64 d; asm("fma.rn.f32x2 %0, %1, %2, %3;" : "=l"(d) : "l"(a), "l"(b), "l"(c)); return d;
}
__device__ __forceinline__ float tanh_fast(float x) {
    float y; asm("tanh.approx.f32 %0, %1;" : "=f"(y) : "f"(x)); return y;
}
__device__ __forceinline__ float sig_fast(float x) {
    return fmaf(0.5f, tanh_fast(0.5f * x), 0.5f);
}

// ---------------------------------------------------------------------------
// Input GEMM: out[m,g] = sum_k A[m,k]*W[g,k] + b1[g] + b2[g]
// 128m x 64n tile, kc=32 double-buffered, 256 threads, 4m x 8n microtile.
// ---------------------------------------------------------------------------
template <int K, bool X_LAYOUT>
__global__ __launch_bounds__(256) void gemm_in_kernel(
    const float* __restrict__ A, const float* __restrict__ W,
    const float* __restrict__ b1, const float* __restrict__ b2,
    float* __restrict__ out)
{
    constexpr int KC = 32;
    constexpr int NC = K / KC;
    constexpr int SA = KC + 1;   // A tile row stride (m-major [128][SA])
    constexpr int SW = 66;       // W tile k-row stride ([KC][SW]), 8B-aligned pairs

    extern __shared__ float sm[];
    float* As = sm;                      // [2][128*SA]
    float* Ws = sm + 2 * 128 * SA;       // [2][KC*SW]

    const int tid = threadIdx.x;
    const int mt  = blockIdx.x;
    const int nt  = blockIdx.y;

    const int kk  = tid & 31;            // staging k within chunk
    const int mr0 = tid >> 5;            // staging A row base (stride 8)
    const int nr0 = tid >> 5;            // staging W row base (stride 8)

    float aR[16], wR[8];

    auto ldg_chunk = [&](int c) {
        const int k0 = c * KC;
#pragma unroll
        for (int j = 0; j < 16; j++) {
            int mrow = mr0 + 8 * j;
            int m = mt * 128 + mrow;
            const float* arow;
            if (X_LAYOUT) {
                int s = m >> 8, b = m & 255;
                arow = A + ((size_t)b * Sd + s) * K;
            } else {
                arow = A + (size_t)m * K;
            }
            aR[j] = arow[k0 + kk];
        }
#pragma unroll
        for (int j = 0; j < 8; j++) {
            int ni = nr0 + 8 * j;
            wR[j] = W[(size_t)(nt * 64 + ni) * K + k0 + kk];
        }
    };
    auto sts_chunk = [&](int buf) {
        float* Ab = As + buf * 128 * SA;
        float* Wb = Ws + buf * KC * SW;
#pragma unroll
        for (int j = 0; j < 16; j++) Ab[(mr0 + 8 * j) * SA + kk] = aR[j];
#pragma unroll
        for (int j = 0; j < 8; j++)  Wb[kk * SW + nr0 + 8 * j] = wR[j];
    };

    const int m0 = (tid >> 3) * 4;
    const int n0 = (tid & 7) * 8;

    u64 acc[4][4];
#pragma unroll
    for (int i = 0; i < 4; i++)
#pragma unroll
        for (int j = 0; j < 4; j++) acc[i][j] = 0ULL;

    ldg_chunk(0);
    sts_chunk(0);
    __syncthreads();

    for (int c = 0; c < NC; c++) {
        if (c + 1 < NC) ldg_chunk(c + 1);

        const float* Ab = As + (c & 1) * 128 * SA;
        const float* Wb = Ws + (c & 1) * KC * SW;
#pragma unroll
        for (int k = 0; k < KC; k++) {
            const u64* wp = (const u64*)&Wb[k * SW + n0];
            u64 w0 = wp[0], w1 = wp[1], w2 = wp[2], w3 = wp[3];
#pragma unroll
            for (int i = 0; i < 4; i++) {
                float a = Ab[(m0 + i) * SA + k];
                u64 av = pack2(a, a);
                acc[i][0] = fma2(av, w0, acc[i][0]);
                acc[i][1] = fma2(av, w1, acc[i][1]);
                acc[i][2] = fma2(av, w2, acc[i][2]);
                acc[i][3] = fma2(av, w3, acc[i][3]);
            }
        }
        if (c + 1 < NC) {
            __syncthreads();
            sts_chunk((c + 1) & 1);
            __syncthreads();
        }
    }

    const int g0 = nt * 64 + n0;
    float bias[8];
#pragma unroll
    for (int j = 0; j < 8; j++) bias[j] = b1[g0 + j] + b2[g0 + j];

#pragma unroll
    for (int i = 0; i < 4; i++) {
        float o[8];
#pragma unroll
        for (int j = 0; j < 4; j++) unpack2(acc[i][j], o[2 * j], o[2 * j + 1]);
        float4 v0, v1;
        v0.x = o[0] + bias[0]; v0.y = o[1] + bias[1];
        v0.z = o[2] + bias[2]; v0.w = o[3] + bias[3];
        v1.x = o[4] + bias[4]; v1.y = o[5] + bias[5];
        v1.z = o[6] + bias[6]; v1.w = o[7] + bias[7];
        size_t m = (size_t)mt * 128 + m0 + i;
        *(float4*)&out[m * Gd + g0]     = v0;
        *(float4*)&out[m * Gd + g0 + 4] = v1;
    }
}

// ---------------------------------------------------------------------------
// LSTM recurrence. 512 threads, BPC=2, grid 128.
// Quad {4u..4u+3} owns gate cols {u, H+u, 2H+u, 3H+u} (i,f,g,o of unit u).
// Whh[col][0:64] in regs (32 pairs); [64:128] in smem [i4][threadid] as 16B
// quads. h double-buffered in smem, read as ulonglong2 broadcasts.
// Epilogue via intra-quad shfl; ONE barrier per step.
// ---------------------------------------------------------------------------
__global__ __launch_bounds__(REC_THREADS, 1) void lstm_rec_kernel(
    const float* __restrict__ xg, const float* __restrict__ Whh,
    float* __restrict__ y_all, float* __restrict__ y_last)
{
    extern __shared__ float smem[];
    ulonglong2* Wsh4 = (ulonglong2*)smem;        // [16][512] : k-quad i4 for thread t
    float* hbuf = smem + 16 * Gd * 4;            // [2][BPC][Hd]

    const int t  = threadIdx.x;
    const int r  = t & 3;
    const int u  = t >> 2;
    const int col = r * Hd + u;
    const int b0 = blockIdx.x * BPC;
    const int qb = (t & 31) & ~3;                // quad base lane in warp

    // Register weights: Whh[col][0:64] as 32 pairs
    u64 wreg[32];
    {
        const u64* wrow = (const u64*)(Whh + (size_t)col * Hd);
#pragma unroll
        for (int i = 0; i < 32; i++) wreg[i] = wrow[i];
    }
    // Smem weights: Wsh4[i4*512 + tt] = Whh[col(tt)][64+4*i4 .. +3]
    for (int idx = t; idx < 16 * Gd; idx += REC_THREADS) {
        int i4 = idx >> 9, tt = idx & 511;
        int cc = (tt & 3) * Hd + (tt >> 2);
        Wsh4[idx] = *(const ulonglong2*)(Whh + (size_t)cc * Hd + 64 + 4 * i4);
    }
    hbuf[t] = 0.0f;   // zero both h buffers (2*BPC*Hd = 512 floats)

    float creg = 0.0f;
    __syncthreads();

    float xv0 = xg[(size_t)b0 * Gd + col];
    float xv1 = xg[((size_t)b0 + 1) * Gd + col];

    for (int s = 0; s < Sd; s++) {
        float nx0 = 0.0f, nx1 = 0.0f;
        if (s + 1 < Sd) {   // prefetch next step's x-preactivations
            nx0 = xg[((size_t)(s + 1) * Bd + b0) * Gd + col];
            nx1 = xg[((size_t)(s + 1) * Bd + b0 + 1) * Gd + col];
        }
        const int p = s & 1;
        const ulonglong2* h0 = (const ulonglong2*)(hbuf + p * (BPC * Hd));
        const ulonglong2* h1 = (const ulonglong2*)(hbuf + p * (BPC * Hd) + Hd);

        u64 a0a = 0ULL, a0b = 0ULL, a1a = 0ULL, a1b = 0ULL;
#pragma unroll
        for (int i4 = 0; i4 < 16; i4++) {       // k = 0..63 (register weights)
            ulonglong2 hA = h0[i4], hB = h1[i4];
            a0a = fma2(wreg[2 * i4],     hA.x, a0a);
            a1a = fma2(wreg[2 * i4],     hB.x, a1a);
            a0b = fma2(wreg[2 * i4 + 1], hA.y, a0b);
            a1b = fma2(wreg[2 * i4 + 1], hB.y, a1b);
        }
#pragma unroll
        for (int i4 = 0; i4 < 16; i4++) {       // k = 64..127 (smem weights)
            ulonglong2 wv = Wsh4[i4 * Gd + t];
            ulonglong2 hA = h0[16 + i4], hB = h1[16 + i4];
            a0a = fma2(wv.x, hA.x, a0a);
            a1a = fma2(wv.x, hB.x, a1a);
            a0b = fma2(wv.y, hA.y, a0b);
            a1b = fma2(wv.y, hB.y, a1b);
        }

        float e0, f0, e1, f1, e2, f2, e3, f3;
        unpack2(a0a, e0, f0); unpack2(a0b, e1, f1);
        unpack2(a1a, e2, f2); unpack2(a1b, e3, f3);
        float p0 = xv0 + (e0 + f0) + (e1 + f1);   // gate preact, batch0
        float p1 = xv1 + (e2 + f2) + (e3 + f3);   // batch1

        // per-lane activation (r==2 is tanh gate)
        float v0 = (r == 2) ? tanh_fast(p0) : sig_fast(p0);
        float v1 = (r == 2) ? tanh_fast(p1) : sig_fast(p1);

        // quad transpose via shfl: gather i,f,g,o for both batches
        float i0 = __shfl_sync(0xffffffffu, v0, qb + 0);
        float ff0 = __shfl_sync(0xffffffffu, v0, qb + 1);
        float gg0 = __shfl_sync(0xffffffffu, v0, qb + 2);
        float o0 = __shfl_sync(0xffffffffu, v0, qb + 3);
        float i1 = __shfl_sync(0xffffffffu, v1, qb + 0);
        float ff1 = __shfl_sync(0xffffffffu, v1, qb + 1);
        float gg1 = __shfl_sync(0xffffffffu, v1, qb + 2);
        float o1 = __shfl_sync(0xffffffffu, v1, qb + 3);

        // lane r==0 owns (batch0, u); lane r==1 owns (batch1, u)
        float iv = (r == 0) ? i0 : i1;
        float fv = (r == 0) ? ff0 : ff1;
        float gv = (r == 0) ? gg0 : gg1;
        float ov = (r == 0) ? o0 : o1;
        creg = fmaf(fv, creg, iv * gv);
        float hn = ov * tanh_fast(creg);

        float* hnext = hbuf + (p ^ 1) * (BPC * Hd);
        if (r < 2) {
            hnext[r * Hd + u] = hn;
            if (y_all) {
                y_all[((size_t)s * Bd + b0 + r) * Hd + u] = hn;
            } else if (s == Sd - 1) {
                y_last[(size_t)(b0 + r) * Hd + u] = hn;
            }
        }
        xv0 = nx0; xv1 = nx1;
        __syncthreads();
    }
}

// ---------------------------------------------------------------------------
extern "C" void kernel_launch(void* const* d_in, const int* in_sizes, int n_in,
                              void* d_out, int out_size)
{
    const float* x    = (const float*)d_in[0];
    const float* Wih0 = (const float*)d_in[1];
    const float* Whh0 = (const float*)d_in[2];
    const float* bih0 = (const float*)d_in[3];
    const float* bhh0 = (const float*)d_in[4];
    const float* Wih1 = (const float*)d_in[5];
    const float* Whh1 = (const float*)d_in[6];
    const float* bih1 = (const float*)d_in[7];
    const float* bhh1 = (const float*)d_in[8];
    float* out = (float*)d_out;

    float* xg = nullptr;
    float* y1 = nullptr;
    cudaGetSymbolAddress((void**)&xg, g_xg);
    cudaGetSymbolAddress((void**)&y1, g_y1);

    const int smem_gemm = (2 * 128 * 33 + 2 * 32 * 66) * (int)sizeof(float);   // ~50 KB
    const int smem_rec  = 16 * Gd * 16 + 2 * BPC * Hd * (int)sizeof(float);    // ~133 KB

    cudaFuncSetAttribute((const void*)gemm_in_kernel<Cd, true>,
                         cudaFuncAttributeMaxDynamicSharedMemorySize, smem_gemm);
    cudaFuncSetAttribute((const void*)gemm_in_kernel<Hd, false>,
                         cudaFuncAttributeMaxDynamicSharedMemorySize, smem_gemm);
    cudaFuncSetAttribute((const void*)lstm_rec_kernel,
                         cudaFuncAttributeMaxDynamicSharedMemorySize, smem_rec);

    dim3 ggrid((Sd * Bd) / 128, Gd / 64);

    gemm_in_kernel<Cd, true><<<ggrid, 256, smem_gemm>>>(x, Wih0, bih0, bhh0, xg);
    lstm_rec_kernel<<<Bd / BPC, REC_THREADS, smem_rec>>>(xg, Whh0, y1, nullptr);

    gemm_in_kernel<Hd, false><<<ggrid, 256, smem_gemm>>>(y1, Wih1, bih1, bhh1, xg);
    lstm_rec_kernel<<<Bd / BPC, REC_THREADS, smem_rec>>>(xg, Whh1, nullptr, out);
}

// round 5
// speedup vs baseline: 1.7966x; 1.2871x over previous
#include <cuda_runtime.h>
#include <cstdint>

#define Bd 256
#define Sd 512
#define Cd 64
#define Hd 128
#define Gd 512
#define REC_THREADS 256
#define KR 80         // k-range held in registers per column
#define QR 20         // KR/4 quads
#define QS 12         // (128-KR)/4 quads from smem

typedef unsigned long long u64;

__device__ float g_xg[(size_t)Sd * Bd * Gd];
__device__ float g_y1[(size_t)Sd * Bd * Hd];

__device__ __forceinline__ u64 pack2(float x, float y) {
    u64 r; asm("mov.b64 %0, {%1,%2};" : "=l"(r) : "f"(x), "f"(y)); return r;
}
__device__ __forceinline__ void unpack2(u64 v, float& x, float& y) {
    asm("mov.b64 {%0,%1}, %2;" : "=f"(x), "=f"(y) : "l"(v));
}
__device__ __forceinline__ u64 fma2(u64 a, u64 b, u64 c) {
    u64 d; asm("fma.rn.f32x2 %0, %1, %2, %3;" : "=l"(d) : "l"(a), "l"(b), "l"(c)); return d;
}
__device__ __forceinline__ float tanh_fast(float x) {
    float y; asm("tanh.approx.f32 %0, %1;" : "=f"(y) : "f"(x)); return y;
}
__device__ __forceinline__ float hsum2(u64 v) {
    float a, b; unpack2(v, a, b); return a + b;
}

// ---------------------------------------------------------------------------
// Input GEMM (unchanged from round 4): 128m x 64n tile, kc=32 double-buffered.
// ---------------------------------------------------------------------------
template <int K, bool X_LAYOUT>
__global__ __launch_bounds__(256) void gemm_in_kernel(
    const float* __restrict__ A, const float* __restrict__ W,
    const float* __restrict__ b1, const float* __restrict__ b2,
    float* __restrict__ out)
{
    constexpr int KC = 32;
    constexpr int NC = K / KC;
    constexpr int SA = KC + 1;
    constexpr int SW = 66;

    extern __shared__ float sm[];
    float* As = sm;
    float* Ws = sm + 2 * 128 * SA;

    const int tid = threadIdx.x;
    const int mt  = blockIdx.x;
    const int nt  = blockIdx.y;

    const int kk  = tid & 31;
    const int mr0 = tid >> 5;
    const int nr0 = tid >> 5;

    float aR[16], wR[8];

    auto ldg_chunk = [&](int c) {
        const int k0 = c * KC;
#pragma unroll
        for (int j = 0; j < 16; j++) {
            int mrow = mr0 + 8 * j;
            int m = mt * 128 + mrow;
            const float* arow;
            if (X_LAYOUT) {
                int s = m >> 8, b = m & 255;
                arow = A + ((size_t)b * Sd + s) * K;
            } else {
                arow = A + (size_t)m * K;
            }
            aR[j] = arow[k0 + kk];
        }
#pragma unroll
        for (int j = 0; j < 8; j++) {
            int ni = nr0 + 8 * j;
            wR[j] = W[(size_t)(nt * 64 + ni) * K + k0 + kk];
        }
    };
    auto sts_chunk = [&](int buf) {
        float* Ab = As + buf * 128 * SA;
        float* Wb = Ws + buf * KC * SW;
#pragma unroll
        for (int j = 0; j < 16; j++) Ab[(mr0 + 8 * j) * SA + kk] = aR[j];
#pragma unroll
        for (int j = 0; j < 8; j++)  Wb[kk * SW + nr0 + 8 * j] = wR[j];
    };

    const int m0 = (tid >> 3) * 4;
    const int n0 = (tid & 7) * 8;

    u64 acc[4][4];
#pragma unroll
    for (int i = 0; i < 4; i++)
#pragma unroll
        for (int j = 0; j < 4; j++) acc[i][j] = 0ULL;

    ldg_chunk(0);
    sts_chunk(0);
    __syncthreads();

    for (int c = 0; c < NC; c++) {
        if (c + 1 < NC) ldg_chunk(c + 1);

        const float* Ab = As + (c & 1) * 128 * SA;
        const float* Wb = Ws + (c & 1) * KC * SW;
#pragma unroll
        for (int k = 0; k < KC; k++) {
            const u64* wp = (const u64*)&Wb[k * SW + n0];
            u64 w0 = wp[0], w1 = wp[1], w2 = wp[2], w3 = wp[3];
#pragma unroll
            for (int i = 0; i < 4; i++) {
                float a = Ab[(m0 + i) * SA + k];
                u64 av = pack2(a, a);
                acc[i][0] = fma2(av, w0, acc[i][0]);
                acc[i][1] = fma2(av, w1, acc[i][1]);
                acc[i][2] = fma2(av, w2, acc[i][2]);
                acc[i][3] = fma2(av, w3, acc[i][3]);
            }
        }
        if (c + 1 < NC) {
            __syncthreads();
            sts_chunk((c + 1) & 1);
            __syncthreads();
        }
    }

    const int g0 = nt * 64 + n0;
    float bias[8];
#pragma unroll
    for (int j = 0; j < 8; j++) bias[j] = b1[g0 + j] + b2[g0 + j];

#pragma unroll
    for (int i = 0; i < 4; i++) {
        float o[8];
#pragma unroll
        for (int j = 0; j < 4; j++) unpack2(acc[i][j], o[2 * j], o[2 * j + 1]);
        float4 v0, v1;
        v0.x = o[0] + bias[0]; v0.y = o[1] + bias[1];
        v0.z = o[2] + bias[2]; v0.w = o[3] + bias[3];
        v1.x = o[4] + bias[4]; v1.y = o[5] + bias[5];
        v1.z = o[6] + bias[6]; v1.w = o[7] + bias[7];
        size_t m = (size_t)mt * 128 + m0 + i;
        *(float4*)&out[m * Gd + g0]     = v0;
        *(float4*)&out[m * Gd + g0 + 4] = v1;
    }
}

// ---------------------------------------------------------------------------
// LSTM recurrence: 256 threads, 2 batches, 2 cols/thread.
// Thread t = 2u+p: p=0 owns (i_u, g_u) cols {u, 256+u};
//                  p=1 owns (f_u, o_u) cols {128+u, 384+u}.
// Weights k<80 in registers (160 regs), k>=80 in smem (48 KB/step traffic).
// h double-buffered in smem (batch-major, pad 132), broadcast quad reads.
// Epilogue: 2x shfl.xor(1) between adjacent lanes; ONE barrier per step.
// ---------------------------------------------------------------------------
__global__ __launch_bounds__(REC_THREADS, 1) void lstm_rec_kernel(
    const float* __restrict__ xg, const float* __restrict__ Whh,
    float* __restrict__ y_all, float* __restrict__ y_last)
{
    extern __shared__ char smraw[];
    ulonglong2* Wq = (ulonglong2*)smraw;                  // [QS*2][256] 16B quads
    float* hb = (float*)(smraw + (size_t)QS * 2 * 256 * 16);  // [2][2][132]

    const int t = threadIdx.x;
    const int u = t >> 1;
    const int p = t & 1;
    const int col0 = p * 128 + u;          // i (p=0) / f (p=1)
    const int col1 = 256 + p * 128 + u;    // g (p=0) / o (p=1)
    const int b0 = blockIdx.x * 2;

    // Register weights: k in [0, KR) for both columns
    u64 wA[2 * QR], wB[2 * QR];
    {
        const u64* rowA = (const u64*)(Whh + (size_t)col0 * Hd);
        const u64* rowB = (const u64*)(Whh + (size_t)col1 * Hd);
#pragma unroll
        for (int j = 0; j < 2 * QR; j++) { wA[j] = rowA[j]; wB[j] = rowB[j]; }
    }
    // Smem weights: k in [KR, 128), laid out [quad-slot][thread] (seq 16B/lane)
#pragma unroll
    for (int j = 0; j < QS; j++) {
        Wq[(j * 2 + 0) * 256 + t] = *(const ulonglong2*)(Whh + (size_t)col0 * Hd + KR + 4 * j);
        Wq[(j * 2 + 1) * 256 + t] = *(const ulonglong2*)(Whh + (size_t)col1 * Hd + KR + 4 * j);
    }
    for (int i = t; i < 2 * 2 * 132; i += REC_THREADS) hb[i] = 0.0f;

    float c = 0.0f;
    __syncthreads();

    float xv00 = xg[(size_t)(b0)*Gd + col0];
    float xv01 = xg[(size_t)(b0 + 1) * Gd + col0];
    float xv10 = xg[(size_t)(b0)*Gd + col1];
    float xv11 = xg[(size_t)(b0 + 1) * Gd + col1];

    for (int s = 0; s < Sd; s++) {
        float n00 = 0.f, n01 = 0.f, n10 = 0.f, n11 = 0.f;
        if (s + 1 < Sd) {
            size_t base = (size_t)(s + 1) * Bd + b0;
            n00 = xg[base * Gd + col0];
            n01 = xg[(base + 1) * Gd + col0];
            n10 = xg[base * Gd + col1];
            n11 = xg[(base + 1) * Gd + col1];
        }
        const int ph = s & 1;
        const ulonglong2* hq0 = (const ulonglong2*)(hb + (ph * 2 + 0) * 132);
        const ulonglong2* hq1 = (const ulonglong2*)(hb + (ph * 2 + 1) * 132);

        u64 a00e = 0, a00o = 0, a01e = 0, a01o = 0;
        u64 a10e = 0, a10o = 0, a11e = 0, a11o = 0;

#pragma unroll
        for (int j = 0; j < QR; j++) {            // k = 4j .. 4j+3 (registers)
            ulonglong2 hA = hq0[j], hB = hq1[j];
            a00e = fma2(wA[2 * j], hA.x, a00e);
            a00o = fma2(wA[2 * j + 1], hA.y, a00o);
            a01e = fma2(wA[2 * j], hB.x, a01e);
            a01o = fma2(wA[2 * j + 1], hB.y, a01o);
            a10e = fma2(wB[2 * j], hA.x, a10e);
            a10o = fma2(wB[2 * j + 1], hA.y, a10o);
            a11e = fma2(wB[2 * j], hB.x, a11e);
            a11o = fma2(wB[2 * j + 1], hB.y, a11o);
        }
#pragma unroll
        for (int j = 0; j < QS; j++) {            // k = KR+4j .. (smem)
            ulonglong2 w0 = Wq[(j * 2 + 0) * 256 + t];
            ulonglong2 w1 = Wq[(j * 2 + 1) * 256 + t];
            ulonglong2 hA = hq0[QR + j], hB = hq1[QR + j];
            a00e = fma2(w0.x, hA.x, a00e);
            a00o = fma2(w0.y, hA.y, a00o);
            a01e = fma2(w0.x, hB.x, a01e);
            a01o = fma2(w0.y, hB.y, a01o);
            a10e = fma2(w1.x, hA.x, a10e);
            a10o = fma2(w1.y, hA.y, a10o);
            a11e = fma2(w1.x, hB.x, a11e);
            a11o = fma2(w1.y, hB.y, a11o);
        }

        float p00 = xv00 + hsum2(a00e) + hsum2(a00o);  // col0, batch0
        float p01 = xv01 + hsum2(a01e) + hsum2(a01o);  // col0, batch1
        float p10 = xv10 + hsum2(a10e) + hsum2(a10o);  // col1, batch0
        float p11 = xv11 + hsum2(a11e) + hsum2(a11o);  // col1, batch1

        // col0 (i or f): always sigmoid
        float v00 = fmaf(0.5f, tanh_fast(0.5f * p00), 0.5f);
        float v01 = fmaf(0.5f, tanh_fast(0.5f * p01), 0.5f);
        // col1: tanh for p=0 (g), sigmoid for p=1 (o)
        float a10s = (p == 0) ? p10 : 0.5f * p10;
        float a11s = (p == 0) ? p11 : 0.5f * p11;
        float t10 = tanh_fast(a10s);
        float t11 = tanh_fast(a11s);
        float v10 = (p == 0) ? t10 : fmaf(0.5f, t10, 0.5f);
        float v11 = (p == 0) ? t11 : fmaf(0.5f, t11, 0.5f);

        // exchange with partner lane (t^1): p=0 keeps batch0, p=1 keeps batch1
        float send1 = (p == 0) ? v01 : v00;   // p0 sends i_b1 ; p1 sends f_b0
        float send2 = (p == 0) ? v11 : v10;   // p0 sends g_b1 ; p1 sends o_b0
        float got1 = __shfl_xor_sync(0xffffffffu, send1, 1);
        float got2 = __shfl_xor_sync(0xffffffffu, send2, 1);

        float iv = (p == 0) ? v00 : got1;
        float fv = (p == 0) ? got1 : v01;
        float gv = (p == 0) ? v10 : got2;
        float ov = (p == 0) ? got2 : v11;

        c = fmaf(fv, c, iv * gv);
        float hn = ov * tanh_fast(c);

        hb[((ph ^ 1) * 2 + p) * 132 + u] = hn;
        if (y_all) {
            y_all[((size_t)s * Bd + b0 + p) * Hd + u] = hn;
        } else if (s == Sd - 1) {
            y_last[(size_t)(b0 + p) * Hd + u] = hn;
        }

        xv00 = n00; xv01 = n01; xv10 = n10; xv11 = n11;
        __syncthreads();
    }
}

// ---------------------------------------------------------------------------
extern "C" void kernel_launch(void* const* d_in, const int* in_sizes, int n_in,
                              void* d_out, int out_size)
{
    const float* x    = (const float*)d_in[0];
    const float* Wih0 = (const float*)d_in[1];
    const float* Whh0 = (const float*)d_in[2];
    const float* bih0 = (const float*)d_in[3];
    const float* bhh0 = (const float*)d_in[4];
    const float* Wih1 = (const float*)d_in[5];
    const float* Whh1 = (const float*)d_in[6];
    const float* bih1 = (const float*)d_in[7];
    const float* bhh1 = (const float*)d_in[8];
    float* out = (float*)d_out;

    float* xg = nullptr;
    float* y1 = nullptr;
    cudaGetSymbolAddress((void**)&xg, g_xg);
    cudaGetSymbolAddress((void**)&y1, g_y1);

    const int smem_gemm = (2 * 128 * 33 + 2 * 32 * 66) * (int)sizeof(float);
    const int smem_rec  = QS * 2 * 256 * 16 + 2 * 2 * 132 * (int)sizeof(float); // ~100 KB

    cudaFuncSetAttribute((const void*)gemm_in_kernel<Cd, true>,
                         cudaFuncAttributeMaxDynamicSharedMemorySize, smem_gemm);
    cudaFuncSetAttribute((const void*)gemm_in_kernel<Hd, false>,
                         cudaFuncAttributeMaxDynamicSharedMemorySize, smem_gemm);
    cudaFuncSetAttribute((const void*)lstm_rec_kernel,
                         cudaFuncAttributeMaxDynamicSharedMemorySize, smem_rec);

    dim3 ggrid((Sd * Bd) / 128, Gd / 64);

    gemm_in_kernel<Cd, true><<<ggrid, 256, smem_gemm>>>(x, Wih0, bih0, bhh0, xg);
    lstm_rec_kernel<<<Bd / 2, REC_THREADS, smem_rec>>>(xg, Whh0, y1, nullptr);

    gemm_in_kernel<Hd, false><<<ggrid, 256, smem_gemm>>>(y1, Wih1, bih1, bhh1, xg);
    lstm_rec_kernel<<<Bd / 2, REC_THREADS, smem_rec>>>(xg, Whh1, nullptr, out);
}

// round 6
// speedup vs baseline: 2.3219x; 1.2923x over previous
#include <cuda_runtime.h>
#include <cstdint>

#define Bd 256
#define Sd 512
#define Cd 64
#define Hd 128
#define Gd 512
#define REC_THREADS 256
#define KR 80
#define QR 20
#define QS 12

typedef unsigned long long u64;
typedef unsigned int u32;

__device__ float g_xg[(size_t)Sd * Bd * Gd];
__device__ float g_y1[(size_t)Sd * Bd * Hd];

__device__ __forceinline__ u64 pack2(float x, float y) {
    u64 r; asm("mov.b64 %0, {%1,%2};" : "=l"(r) : "f"(x), "f"(y)); return r;
}
__device__ __forceinline__ void unpack2(u64 v, float& x, float& y) {
    asm("mov.b64 {%0,%1}, %2;" : "=f"(x), "=f"(y) : "l"(v));
}
__device__ __forceinline__ u64 fma2(u64 a, u64 b, u64 c) {
    u64 d; asm("fma.rn.f32x2 %0, %1, %2, %3;" : "=l"(d) : "l"(a), "l"(b), "l"(c)); return d;
}
__device__ __forceinline__ float tanh_fast(float x) {
    float y; asm("tanh.approx.f32 %0, %1;" : "=f"(y) : "f"(x)); return y;
}
__device__ __forceinline__ float hsum2(u64 v) {
    float a, b; unpack2(v, a, b); return a + b;
}
__device__ __forceinline__ u32 to_tf32(float x) {
    u32 r; asm("cvt.rna.tf32.f32 %0, %1;" : "=r"(r) : "f"(x)); return r;
}
__device__ __forceinline__ void mma_tf32(
    float& c0, float& c1, float& c2, float& c3,
    u32 a0, u32 a1, u32 a2, u32 a3, u32 b0, u32 b1)
{
    asm("mma.sync.aligned.m16n8k8.row.col.f32.tf32.tf32.f32 "
        "{%0,%1,%2,%3}, {%4,%5,%6,%7}, {%8,%9}, {%0,%1,%2,%3};"
        : "+f"(c0), "+f"(c1), "+f"(c2), "+f"(c3)
        : "r"(a0), "r"(a1), "r"(a2), "r"(a3), "r"(b0), "r"(b1));
}

// ---------------------------------------------------------------------------
// TF32 input GEMM: out[m,g] = sum_k A[m,k]*W[g,k] + b1[g] + b2[g]
// CTA tile 128m x 64n, whole K resident in smem (tf32), 256 threads.
// Warps: 4(m) x 2(n); per warp 32m x 32n = 2 x 4 m16n8k8 tiles.
// A smem [m][K+4] row-major; W smem [n][K+4] (k contiguous = mma .col B).
// Fragment LDS banks: (4*gID + tig) mod 32 all-distinct -> conflict-free.
// X_LAYOUT=true: A is x (B,S,C), row for m=(s*Bd+b) at (b*Sd+s)*K.
// ---------------------------------------------------------------------------
template <int K, bool X_LAYOUT>
__global__ __launch_bounds__(256) void gemm_tf32_kernel(
    const float* __restrict__ A, const float* __restrict__ W,
    const float* __restrict__ b1, const float* __restrict__ b2,
    float* __restrict__ out)
{
    constexpr int SK = K + 4;
    extern __shared__ u32 sm32[];
    u32* As = sm32;               // [128][SK]
    u32* Bs = sm32 + 128 * SK;    // [64][SK]

    const int tid = threadIdx.x;
    const int mt  = blockIdx.x;
    const int nt  = blockIdx.y;

    // ---- fill A (coalesced float4, cvt to tf32) ----
    for (int i = tid; i < 128 * (K / 4); i += 256) {
        int row = i / (K / 4);
        int q   = i % (K / 4);
        int m   = mt * 128 + row;
        const float4* src;
        if (X_LAYOUT) {
            int s = m >> 8, b = m & 255;
            src = (const float4*)(A + ((size_t)b * Sd + s) * K);
        } else {
            src = (const float4*)(A + (size_t)m * K);
        }
        float4 v = src[q];
        u32* dst = &As[row * SK + 4 * q];
        dst[0] = to_tf32(v.x); dst[1] = to_tf32(v.y);
        dst[2] = to_tf32(v.z); dst[3] = to_tf32(v.w);
    }
    // ---- fill W ----
    for (int i = tid; i < 64 * (K / 4); i += 256) {
        int row = i / (K / 4);
        int q   = i % (K / 4);
        const float4* src = (const float4*)(W + (size_t)(nt * 64 + row) * K);
        float4 v = src[q];
        u32* dst = &Bs[row * SK + 4 * q];
        dst[0] = to_tf32(v.x); dst[1] = to_tf32(v.y);
        dst[2] = to_tf32(v.z); dst[3] = to_tf32(v.w);
    }
    __syncthreads();

    const int wid  = tid >> 5;
    const int lane = tid & 31;
    const int gID  = lane >> 2;
    const int tig  = lane & 3;
    const int wm   = (wid >> 1) * 32;    // warp m offset in tile
    const int wn   = (wid & 1) * 32;     // warp n offset in tile

    float c[2][4][4];
#pragma unroll
    for (int i = 0; i < 2; i++)
#pragma unroll
        for (int j = 0; j < 4; j++)
#pragma unroll
            for (int q = 0; q < 4; q++) c[i][j][q] = 0.0f;

#pragma unroll
    for (int kb = 0; kb < K / 8; kb++) {
        const int k0 = kb * 8;
        u32 a[2][4];
#pragma unroll
        for (int mi = 0; mi < 2; mi++) {
            int r = wm + mi * 16 + gID;
            a[mi][0] = As[r * SK + k0 + tig];
            a[mi][1] = As[(r + 8) * SK + k0 + tig];
            a[mi][2] = As[r * SK + k0 + tig + 4];
            a[mi][3] = As[(r + 8) * SK + k0 + tig + 4];
        }
        u32 b[4][2];
#pragma unroll
        for (int ni = 0; ni < 4; ni++) {
            int r = wn + ni * 8 + gID;
            b[ni][0] = Bs[r * SK + k0 + tig];
            b[ni][1] = Bs[r * SK + k0 + tig + 4];
        }
#pragma unroll
        for (int mi = 0; mi < 2; mi++)
#pragma unroll
            for (int ni = 0; ni < 4; ni++)
                mma_tf32(c[mi][ni][0], c[mi][ni][1], c[mi][ni][2], c[mi][ni][3],
                         a[mi][0], a[mi][1], a[mi][2], a[mi][3],
                         b[ni][0], b[ni][1]);
    }

    // ---- epilogue: bias + store (float2 per mma tile row) ----
#pragma unroll
    for (int ni = 0; ni < 4; ni++) {
        int g = nt * 64 + wn + ni * 8 + 2 * tig;
        float bx = b1[g] + b2[g];
        float by = b1[g + 1] + b2[g + 1];
#pragma unroll
        for (int mi = 0; mi < 2; mi++) {
            size_t m = (size_t)mt * 128 + wm + mi * 16 + gID;
            float2 v0 = make_float2(c[mi][ni][0] + bx, c[mi][ni][1] + by);
            float2 v1 = make_float2(c[mi][ni][2] + bx, c[mi][ni][3] + by);
            *(float2*)&out[m * Gd + g]       = v0;
            *(float2*)&out[(m + 8) * Gd + g] = v1;
        }
    }
}

// ---------------------------------------------------------------------------
// LSTM recurrence (unchanged from round 5).
// ---------------------------------------------------------------------------
__global__ __launch_bounds__(REC_THREADS, 1) void lstm_rec_kernel(
    const float* __restrict__ xg, const float* __restrict__ Whh,
    float* __restrict__ y_all, float* __restrict__ y_last)
{
    extern __shared__ char smraw[];
    ulonglong2* Wq = (ulonglong2*)smraw;                      // [QS*2][256]
    float* hb = (float*)(smraw + (size_t)QS * 2 * 256 * 16);  // [2][2][132]

    const int t = threadIdx.x;
    const int u = t >> 1;
    const int p = t & 1;
    const int col0 = p * 128 + u;
    const int col1 = 256 + p * 128 + u;
    const int b0 = blockIdx.x * 2;

    u64 wA[2 * QR], wB[2 * QR];
    {
        const u64* rowA = (const u64*)(Whh + (size_t)col0 * Hd);
        const u64* rowB = (const u64*)(Whh + (size_t)col1 * Hd);
#pragma unroll
        for (int j = 0; j < 2 * QR; j++) { wA[j] = rowA[j]; wB[j] = rowB[j]; }
    }
#pragma unroll
    for (int j = 0; j < QS; j++) {
        Wq[(j * 2 + 0) * 256 + t] = *(const ulonglong2*)(Whh + (size_t)col0 * Hd + KR + 4 * j);
        Wq[(j * 2 + 1) * 256 + t] = *(const ulonglong2*)(Whh + (size_t)col1 * Hd + KR + 4 * j);
    }
    for (int i = t; i < 2 * 2 * 132; i += REC_THREADS) hb[i] = 0.0f;

    float c = 0.0f;
    __syncthreads();

    float xv00 = xg[(size_t)(b0)*Gd + col0];
    float xv01 = xg[(size_t)(b0 + 1) * Gd + col0];
    float xv10 = xg[(size_t)(b0)*Gd + col1];
    float xv11 = xg[(size_t)(b0 + 1) * Gd + col1];

    for (int s = 0; s < Sd; s++) {
        float n00 = 0.f, n01 = 0.f, n10 = 0.f, n11 = 0.f;
        if (s + 1 < Sd) {
            size_t base = (size_t)(s + 1) * Bd + b0;
            n00 = xg[base * Gd + col0];
            n01 = xg[(base + 1) * Gd + col0];
            n10 = xg[base * Gd + col1];
            n11 = xg[(base + 1) * Gd + col1];
        }
        const int ph = s & 1;
        const ulonglong2* hq0 = (const ulonglong2*)(hb + (ph * 2 + 0) * 132);
        const ulonglong2* hq1 = (const ulonglong2*)(hb + (ph * 2 + 1) * 132);

        u64 a00e = 0, a00o = 0, a01e = 0, a01o = 0;
        u64 a10e = 0, a10o = 0, a11e = 0, a11o = 0;

#pragma unroll
        for (int j = 0; j < QR; j++) {
            ulonglong2 hA = hq0[j], hB = hq1[j];
            a00e = fma2(wA[2 * j], hA.x, a00e);
            a00o = fma2(wA[2 * j + 1], hA.y, a00o);
            a01e = fma2(wA[2 * j], hB.x, a01e);
            a01o = fma2(wA[2 * j + 1], hB.y, a01o);
            a10e = fma2(wB[2 * j], hA.x, a10e);
            a10o = fma2(wB[2 * j + 1], hA.y, a10o);
            a11e = fma2(wB[2 * j], hB.x, a11e);
            a11o = fma2(wB[2 * j + 1], hB.y, a11o);
        }
#pragma unroll
        for (int j = 0; j < QS; j++) {
            ulonglong2 w0 = Wq[(j * 2 + 0) * 256 + t];
            ulonglong2 w1 = Wq[(j * 2 + 1) * 256 + t];
            ulonglong2 hA = hq0[QR + j], hB = hq1[QR + j];
            a00e = fma2(w0.x, hA.x, a00e);
            a00o = fma2(w0.y, hA.y, a00o);
            a01e = fma2(w0.x, hB.x, a01e);
            a01o = fma2(w0.y, hB.y, a01o);
            a10e = fma2(w1.x, hA.x, a10e);
            a10o = fma2(w1.y, hA.y, a10o);
            a11e = fma2(w1.x, hB.x, a11e);
            a11o = fma2(w1.y, hB.y, a11o);
        }

        float p00 = xv00 + hsum2(a00e) + hsum2(a00o);
        float p01 = xv01 + hsum2(a01e) + hsum2(a01o);
        float p10 = xv10 + hsum2(a10e) + hsum2(a10o);
        float p11 = xv11 + hsum2(a11e) + hsum2(a11o);

        float v00 = fmaf(0.5f, tanh_fast(0.5f * p00), 0.5f);
        float v01 = fmaf(0.5f, tanh_fast(0.5f * p01), 0.5f);
        float a10s = (p == 0) ? p10 : 0.5f * p10;
        float a11s = (p == 0) ? p11 : 0.5f * p11;
        float t10 = tanh_fast(a10s);
        float t11 = tanh_fast(a11s);
        float v10 = (p == 0) ? t10 : fmaf(0.5f, t10, 0.5f);
        float v11 = (p == 0) ? t11 : fmaf(0.5f, t11, 0.5f);

        float send1 = (p == 0) ? v01 : v00;
        float send2 = (p == 0) ? v11 : v10;
        float got1 = __shfl_xor_sync(0xffffffffu, send1, 1);
        float got2 = __shfl_xor_sync(0xffffffffu, send2, 1);

        float iv = (p == 0) ? v00 : got1;
        float fv = (p == 0) ? got1 : v01;
        float gv = (p == 0) ? v10 : got2;
        float ov = (p == 0) ? got2 : v11;

        c = fmaf(fv, c, iv * gv);
        float hn = ov * tanh_fast(c);

        hb[((ph ^ 1) * 2 + p) * 132 + u] = hn;
        if (y_all) {
            y_all[((size_t)s * Bd + b0 + p) * Hd + u] = hn;
        } else if (s == Sd - 1) {
            y_last[(size_t)(b0 + p) * Hd + u] = hn;
        }

        xv00 = n00; xv01 = n01; xv10 = n10; xv11 = n11;
        __syncthreads();
    }
}

// ---------------------------------------------------------------------------
extern "C" void kernel_launch(void* const* d_in, const int* in_sizes, int n_in,
                              void* d_out, int out_size)
{
    const float* x    = (const float*)d_in[0];
    const float* Wih0 = (const float*)d_in[1];
    const float* Whh0 = (const float*)d_in[2];
    const float* bih0 = (const float*)d_in[3];
    const float* bhh0 = (const float*)d_in[4];
    const float* Wih1 = (const float*)d_in[5];
    const float* Whh1 = (const float*)d_in[6];
    const float* bih1 = (const float*)d_in[7];
    const float* bhh1 = (const float*)d_in[8];
    float* out = (float*)d_out;

    float* xg = nullptr;
    float* y1 = nullptr;
    cudaGetSymbolAddress((void**)&xg, g_xg);
    cudaGetSymbolAddress((void**)&y1, g_y1);

    const int smem_g0 = (128 * (Cd + 4) + 64 * (Cd + 4)) * 4;   // ~52 KB
    const int smem_g1 = (128 * (Hd + 4) + 64 * (Hd + 4)) * 4;   // ~101 KB
    const int smem_rec = QS * 2 * 256 * 16 + 2 * 2 * 132 * (int)sizeof(float);

    cudaFuncSetAttribute((const void*)gemm_tf32_kernel<Cd, true>,
                         cudaFuncAttributeMaxDynamicSharedMemorySize, smem_g0);
    cudaFuncSetAttribute((const void*)gemm_tf32_kernel<Hd, false>,
                         cudaFuncAttributeMaxDynamicSharedMemorySize, smem_g1);
    cudaFuncSetAttribute((const void*)lstm_rec_kernel,
                         cudaFuncAttributeMaxDynamicSharedMemorySize, smem_rec);

    dim3 ggrid((Sd * Bd) / 128, Gd / 64);

    gemm_tf32_kernel<Cd, true><<<ggrid, 256, smem_g0>>>(x, Wih0, bih0, bhh0, xg);
    lstm_rec_kernel<<<Bd / 2, REC_THREADS, smem_rec>>>(xg, Whh0, y1, nullptr);

    gemm_tf32_kernel<Hd, false><<<ggrid, 256, smem_g1>>>(y1, Wih1, bih1, bhh1, xg);
    lstm_rec_kernel<<<Bd / 2, REC_THREADS, smem_rec>>>(xg, Whh1, nullptr, out);
}